// round 12
// baseline (speedup 1.0000x reference)
#include <cuda_runtime.h>
#include <cuda_bf16.h>
#include <cuda_fp16.h>
#include <cstdint>

#define DIM 256
#define N_NODES_MAX 50000
#define N_EDGES_MAX 800000
#define ELLW 96              // ELL row width (avg degree 16; P(>96) ~ 0)
#define OVF_CAP 4096

// ----- scratch (__device__ globals; no cudaMalloc allowed) -----
__device__ __half  g_hidden_h[N_NODES_MAX * DIM];     // x @ W (fp16)
__device__ __half  g_WT[DIM * DIM];                   // W^T fp16 (WT[n][k])
__device__ int     g_counts[N_NODES_MAX];             // per-row edge counts
__device__ int2    g_ell[(size_t)N_NODES_MAX * ELLW]; // (col, val-bits) per slot
__device__ int     g_ovf_cnt[1];
__device__ int4    g_ovf[OVF_CAP];                    // (row, col, val-bits, _)

// ---- packed f32x2 helpers (Blackwell FFMA2 path; PTX sm_100+) ----
#define FMA_F32X2(d, a, b, c) \
    asm("fma.rn.f32x2 %0, %1, %2, %3;" : "=l"(d) : "l"(a), "l"(b), "l"(c))
#define PACK_F32X2(out, lo, hi) \
    asm("mov.b64 %0, {%1, %2};" : "=l"(out) : "r"(lo), "r"(hi))
#define UNPACK_F32X2(lo, hi, in) \
    asm("mov.b64 {%0, %1}, %2;" : "=r"(lo), "=r"(hi) : "l"(in))

// ===========================================================================
// Kernel 0: W^T fp16.  WT[n][k] = W[k][n]
// ===========================================================================
__global__ void wt_convert_kernel(const float* __restrict__ W,
                                  __half* __restrict__ wt) {
    int k = blockIdx.x;
    int n = threadIdx.x;
    wt[n * DIM + k] = __float2half_rn(W[k * DIM + n]);
}

// ===========================================================================
// Kernel 1: mma.sync fp16 GEMM. 64-wide N tiles, SINGLE launch grid(4, M/128)
// so the 4 N-CTAs of one M-block are co-resident and share x via L2.
// (unchanged from R11 — measured-good)
// ===========================================================================
#define SA 72
#define SB 264
#define A_OFF 0
#define B_OFF (128 * SA)
#define GEMM_SMEM_BYTES ((128 * SA + 64 * SB) * 2)   // 52224

__device__ __forceinline__ void mma16816(float* c, const uint32_t* a, const uint32_t* b) {
    asm volatile(
        "mma.sync.aligned.m16n8k16.row.col.f32.f16.f16.f32 "
        "{%0,%1,%2,%3}, {%4,%5,%6,%7}, {%8,%9}, {%0,%1,%2,%3};"
        : "+f"(c[0]), "+f"(c[1]), "+f"(c[2]), "+f"(c[3])
        : "r"(a[0]), "r"(a[1]), "r"(a[2]), "r"(a[3]), "r"(b[0]), "r"(b[1]));
}

__global__ __launch_bounds__(256, 2) void gemm_mma_kernel(
        const float* __restrict__ x,
        const __half* __restrict__ wt,
        __half* __restrict__ hidden, int M) {
    extern __shared__ __half sm[];

    const int tid  = threadIdx.x;
    const int warp = tid >> 5;
    const int lane = tid & 31;
    const int gid  = lane >> 2;
    const int tig  = lane & 3;
    const int wm   = warp >> 1;
    const int wn   = warp & 1;
    const int blockM = blockIdx.y * 128;
    const int blockN = blockIdx.x * 64;

#pragma unroll
    for (int t = 0; t < 8; t++) {
        int idx = tid + t * 256;
        int n = idx >> 5;
        int j = idx & 31;
        *reinterpret_cast<uint4*>(&sm[B_OFF + n * SB + j * 8]) =
            *reinterpret_cast<const uint4*>(&wt[(size_t)(blockN + n) * DIM + j * 8]);
    }

    float c[2][4][4];
#pragma unroll
    for (int f = 0; f < 2; f++)
#pragma unroll
        for (int g = 0; g < 4; g++)
#pragma unroll
            for (int q = 0; q < 4; q++) c[f][g][q] = 0.f;

    for (int kc = 0; kc < 4; kc++) {
        __syncthreads();
#pragma unroll
        for (int t = 0; t < 8; t++) {
            int idx = tid + t * 256;
            int row = idx >> 4;
            int c4  = idx & 15;
            float4 v = make_float4(0.f, 0.f, 0.f, 0.f);
            if (blockM + row < M)
                v = *reinterpret_cast<const float4*>(
                        &x[(size_t)(blockM + row) * DIM + kc * 64 + c4 * 4]);
            __half2 p0 = __floats2half2_rn(v.x, v.y);
            __half2 p1 = __floats2half2_rn(v.z, v.w);
            *reinterpret_cast<uint2*>(&sm[A_OFF + row * SA + c4 * 4]) =
                make_uint2(*reinterpret_cast<uint32_t*>(&p0),
                           *reinterpret_cast<uint32_t*>(&p1));
        }
        __syncthreads();

#pragma unroll
        for (int ks = 0; ks < 4; ks++) {
            const int kb = ks * 16;
            uint32_t a[2][4], bb[4][2];
#pragma unroll
            for (int f = 0; f < 2; f++) {
                int r0 = wm * 32 + f * 16;
                a[f][0] = *reinterpret_cast<const uint32_t*>(&sm[A_OFF + (r0 + gid)     * SA + kb + 2 * tig]);
                a[f][1] = *reinterpret_cast<const uint32_t*>(&sm[A_OFF + (r0 + gid + 8) * SA + kb + 2 * tig]);
                a[f][2] = *reinterpret_cast<const uint32_t*>(&sm[A_OFF + (r0 + gid)     * SA + kb + 2 * tig + 8]);
                a[f][3] = *reinterpret_cast<const uint32_t*>(&sm[A_OFF + (r0 + gid + 8) * SA + kb + 2 * tig + 8]);
            }
#pragma unroll
            for (int g = 0; g < 4; g++) {
                int n0 = wn * 32 + g * 8;
                int kk = kc * 64 + kb + 2 * tig;
                bb[g][0] = *reinterpret_cast<const uint32_t*>(&sm[B_OFF + (n0 + gid) * SB + kk]);
                bb[g][1] = *reinterpret_cast<const uint32_t*>(&sm[B_OFF + (n0 + gid) * SB + kk + 8]);
            }
#pragma unroll
            for (int f = 0; f < 2; f++)
#pragma unroll
                for (int g = 0; g < 4; g++)
                    mma16816(c[f][g], a[f], bb[g]);
        }
    }

#pragma unroll
    for (int f = 0; f < 2; f++) {
#pragma unroll
        for (int g = 0; g < 4; g++) {
            int row = blockM + wm * 32 + f * 16 + gid;
            int col = blockN + wn * 32 + g * 8 + 2 * tig;
            if (row < M)
                *reinterpret_cast<__half2*>(&hidden[(size_t)row * DIM + col]) =
                    __floats2half2_rn(c[f][g][0], c[f][g][1]);
            if (row + 8 < M)
                *reinterpret_cast<__half2*>(&hidden[(size_t)(row + 8) * DIM + col]) =
                    __floats2half2_rn(c[f][g][2], c[f][g][3]);
        }
    }
}

// ===========================================================================
// ELL build: ONE scatter kernel.
// ===========================================================================
__global__ void ell_scatter_kernel(const int* __restrict__ rows,
                                   const int* __restrict__ cols,
                                   const float* __restrict__ vals,
                                   int*  __restrict__ counts,
                                   int2* __restrict__ ell,
                                   int*  __restrict__ ovf_cnt,
                                   int4* __restrict__ ovf,
                                   int E) {
    int i = blockIdx.x * blockDim.x + threadIdx.x;
    if (i < E) {
        int r   = rows[i];
        int pos = atomicAdd(&counts[r], 1);
        if (pos < ELLW) {
            ell[(size_t)r * ELLW + pos] = make_int2(cols[i], __float_as_int(vals[i]));
        } else {
            int o = atomicAdd(ovf_cnt, 1);
            if (o < OVF_CAP)
                ovf[o] = make_int4(r, cols[i], __float_as_int(vals[i]), 0);
        }
    }
}

// ===========================================================================
// SpMM: warp per dest row, lane owns 8 dims as 4 packed-f32x2 accumulators.
// Per edge: 1 uint4 gather + 4 cvt-pairs + 4 FFMA2. Metadata via int4
// (2 edges per uniform load). 8-edge unroll => 8 x 16B outstanding/lane.
// ===========================================================================
__device__ __forceinline__ void fma8_x2(uint64_t* acc, uint4 r, uint64_t v2) {
    float2 f0 = __half22float2(*reinterpret_cast<__half2*>(&r.x));
    float2 f1 = __half22float2(*reinterpret_cast<__half2*>(&r.y));
    float2 f2 = __half22float2(*reinterpret_cast<__half2*>(&r.z));
    float2 f3 = __half22float2(*reinterpret_cast<__half2*>(&r.w));
    uint64_t d0, d1, d2, d3;
    PACK_F32X2(d0, __float_as_uint(f0.x), __float_as_uint(f0.y));
    PACK_F32X2(d1, __float_as_uint(f1.x), __float_as_uint(f1.y));
    PACK_F32X2(d2, __float_as_uint(f2.x), __float_as_uint(f2.y));
    PACK_F32X2(d3, __float_as_uint(f3.x), __float_as_uint(f3.y));
    FMA_F32X2(acc[0], d0, v2, acc[0]);
    FMA_F32X2(acc[1], d1, v2, acc[1]);
    FMA_F32X2(acc[2], d2, v2, acc[2]);
    FMA_F32X2(acc[3], d3, v2, acc[3]);
}

__device__ __forceinline__ uint64_t dup_f32x2(int vbits) {
    uint64_t v2;
    PACK_F32X2(v2, (uint32_t)vbits, (uint32_t)vbits);
    return v2;
}

__global__ __launch_bounds__(256) void spmm_ell_kernel(const int*  __restrict__ counts,
                                                       const int2* __restrict__ ell,
                                                       const __half* __restrict__ hidden,
                                                       const float* __restrict__ b,
                                                       float*       __restrict__ out,
                                                       int M) {
    const int w    = (blockIdx.x * blockDim.x + threadIdx.x) >> 5;
    const int lane = threadIdx.x & 31;
    if (w >= M) return;

    const int cnt = min(counts[w], ELLW);
    const int2* erow = ell + (size_t)w * ELLW;

    uint64_t acc[4];
#pragma unroll
    for (int q = 0; q < 4; q++) PACK_F32X2(acc[q], 0u, 0u);
    const __half* hbase = hidden + lane * 8;

    int j = 0;
    for (; j + 7 < cnt; j += 8) {
        int4 m[4];                         // 2 edges per int4
#pragma unroll
        for (int q = 0; q < 4; q++)
            m[q] = *reinterpret_cast<const int4*>(erow + j + 2 * q);
        uint4 r[8];
#pragma unroll
        for (int q = 0; q < 4; q++) {
            r[2 * q]     = *reinterpret_cast<const uint4*>(hbase + (size_t)m[q].x * DIM);
            r[2 * q + 1] = *reinterpret_cast<const uint4*>(hbase + (size_t)m[q].z * DIM);
        }
#pragma unroll
        for (int q = 0; q < 4; q++) {
            fma8_x2(acc, r[2 * q],     dup_f32x2(m[q].y));
            fma8_x2(acc, r[2 * q + 1], dup_f32x2(m[q].w));
        }
    }
    for (; j + 1 < cnt; j += 2) {
        int4 m = *reinterpret_cast<const int4*>(erow + j);
        uint4 r0 = *reinterpret_cast<const uint4*>(hbase + (size_t)m.x * DIM);
        uint4 r1 = *reinterpret_cast<const uint4*>(hbase + (size_t)m.z * DIM);
        fma8_x2(acc, r0, dup_f32x2(m.y));
        fma8_x2(acc, r1, dup_f32x2(m.w));
    }
    if (j < cnt) {
        int2 p0 = erow[j];
        uint4 r0 = *reinterpret_cast<const uint4*>(hbase + (size_t)p0.x * DIM);
        fma8_x2(acc, r0, dup_f32x2(p0.y));
    }

    // unpack + bias + store
    float a[8];
#pragma unroll
    for (int q = 0; q < 4; q++) {
        uint32_t lo, hi;
        UNPACK_F32X2(lo, hi, acc[q]);
        a[2 * q]     = __uint_as_float(lo);
        a[2 * q + 1] = __uint_as_float(hi);
    }
    const float4* b4 = reinterpret_cast<const float4*>(b + lane * 8);
    float4 bb0 = b4[0], bb1 = b4[1];
    float4* o = reinterpret_cast<float4*>(out + (size_t)w * DIM + lane * 8);
    o[0] = make_float4(a[0] + bb0.x, a[1] + bb0.y, a[2] + bb0.z, a[3] + bb0.w);
    o[1] = make_float4(a[4] + bb1.x, a[5] + bb1.y, a[6] + bb1.z, a[7] + bb1.w);
}

// ===========================================================================
// Overflow fixup: normally n==0.
// ===========================================================================
__global__ void ovf_fixup_kernel(const int* __restrict__ ovf_cnt,
                                 const int4* __restrict__ ovf,
                                 const __half* __restrict__ hidden,
                                 float* __restrict__ out) {
    int n = min(*ovf_cnt, OVF_CAP);
    int t = threadIdx.x;
    for (int e = 0; e < n; e++) {
        int4 p = ovf[e];
        float v = __int_as_float(p.z);
        out[(size_t)p.x * DIM + t] =
            fmaf(v, __half2float(hidden[(size_t)p.y * DIM + t]),
                 out[(size_t)p.x * DIM + t]);
    }
}

// ===========================================================================
// Launch (unchanged structure):
//   s_csr  : memsets -> ell_scatter        (|| gemm)
//   default: wt -> gemm (grid 4x391) -> [wait ELL] spmm -> fixup
// ===========================================================================
extern "C" void kernel_launch(void* const* d_in, const int* in_sizes, int n_in,
                              void* d_out, int out_size) {
    const float* x        = (const float*)d_in[0];
    const int*   adj_rows = (const int*)  d_in[1];
    const int*   adj_cols = (const int*)  d_in[2];
    const float* adj_vals = (const float*)d_in[3];
    const float* W        = (const float*)d_in[4];
    const float* b        = (const float*)d_in[5];
    float*       out      = (float*)d_out;

    const int M = in_sizes[0] / DIM;   // 50000
    const int E = in_sizes[1];         // 800000

    __half *hidden, *wt;
    int *counts, *ovf_cnt;
    int2 *ell;
    int4 *ovf;
    cudaGetSymbolAddress((void**)&hidden,  g_hidden_h);
    cudaGetSymbolAddress((void**)&wt,      g_WT);
    cudaGetSymbolAddress((void**)&counts,  g_counts);
    cudaGetSymbolAddress((void**)&ell,     g_ell);
    cudaGetSymbolAddress((void**)&ovf_cnt, g_ovf_cnt);
    cudaGetSymbolAddress((void**)&ovf,     g_ovf);

    static cudaStream_t s_csr = nullptr;
    static cudaEvent_t  ev_fork = nullptr, ev_csr = nullptr;
    if (s_csr == nullptr) {
        cudaStreamCreateWithFlags(&s_csr, cudaStreamNonBlocking);
        cudaEventCreateWithFlags(&ev_fork, cudaEventDisableTiming);
        cudaEventCreateWithFlags(&ev_csr,  cudaEventDisableTiming);
        cudaFuncSetAttribute(gemm_mma_kernel,
                             cudaFuncAttributeMaxDynamicSharedMemorySize, GEMM_SMEM_BYTES);
    }

    // ---- fork: ELL build on s_csr ----
    cudaEventRecord(ev_fork, 0);
    cudaStreamWaitEvent(s_csr, ev_fork, 0);

    cudaMemsetAsync(counts, 0, (size_t)M * sizeof(int), s_csr);
    cudaMemsetAsync(ovf_cnt, 0, sizeof(int), s_csr);
    ell_scatter_kernel<<<(E + 255) / 256, 256, 0, s_csr>>>(adj_rows, adj_cols, adj_vals,
                                                           counts, ell, ovf_cnt, ovf, E);
    cudaEventRecord(ev_csr, s_csr);

    // ---- GEMM (single launch, 4 N-blocks co-resident, x shared via L2) ----
    wt_convert_kernel<<<DIM, DIM>>>(W, wt);
    dim3 gemmGrid(4, (M + 127) / 128);
    gemm_mma_kernel<<<gemmGrid, 256, GEMM_SMEM_BYTES>>>(x, wt, hidden, M);

    // ---- SpMM after GEMM + ELL ----
    cudaStreamWaitEvent(0, ev_csr, 0);
    spmm_ell_kernel<<<(M * 32 + 255) / 256, 256>>>(counts, ell, hidden, b, out, M);
    ovf_fixup_kernel<<<1, 256>>>(ovf_cnt, ovf, hidden, out);
}

// round 14
// speedup vs baseline: 1.0250x; 1.0250x over previous
#include <cuda_runtime.h>
#include <cuda_bf16.h>
#include <cuda_fp16.h>
#include <cstdint>

#define DIM 256
#define N_NODES_MAX 50000
#define N_EDGES_MAX 800000
#define ELLW 96              // ELL row width (avg degree 16; P(>96) ~ 0)
#define OVF_CAP 4096

// ----- scratch (__device__ globals; no cudaMalloc allowed) -----
__device__ __half  g_hidden_h[N_NODES_MAX * DIM];     // x @ W (fp16)
__device__ __half  g_WT[DIM * DIM];                   // W^T fp16 (WT[n][k])
__device__ int     g_counts[N_NODES_MAX];             // per-row edge counts
__device__ int2    g_ell[(size_t)N_NODES_MAX * ELLW]; // (col, val-bits) per slot
__device__ int     g_ovf_cnt[1];
__device__ int4    g_ovf[OVF_CAP];                    // (row, col, val-bits, _)

// ===========================================================================
// Kernel 0: W^T fp16.  WT[n][k] = W[k][n]
// ===========================================================================
__global__ void wt_convert_kernel(const float* __restrict__ W,
                                  __half* __restrict__ wt) {
    int k = blockIdx.x;
    int n = threadIdx.x;
    wt[n * DIM + k] = __float2half_rn(W[k * DIM + n]);
}

// ===========================================================================
// Kernel 1: mma.sync fp16 GEMM. 64-wide N tiles, grid(4, M/128) single
// launch (x shared via L2). K-chunk = 128: 4 syncs/CTA instead of 8, and
// 16 independent float4 LDGs per thread per staging stretch (deep MLP).
// 256 thr = 8 warps (4Mx2N), CTA tile 128x64, warp tile 32x32, 2 CTAs/SM.
// ===========================================================================
#define SA 136    // A smem row stride (128 + 8 pad) in halves
#define SB 264    // B smem row stride (256 + 8 pad) in halves
#define A_OFF 0
#define B_OFF (128 * SA)
#define GEMM_SMEM_BYTES ((128 * SA + 64 * SB) * 2)   // 68608

// NOTE: "+f" outputs serve as both in and out; inputs are %4..%9 = a[0..3], b[0..1].
// (R13 bug: extra duplicate "f"(c[..]) inputs shifted operand numbering.)
__device__ __forceinline__ void mma16816(float* c, const uint32_t* a, const uint32_t* b) {
    asm volatile(
        "mma.sync.aligned.m16n8k16.row.col.f32.f16.f16.f32 "
        "{%0,%1,%2,%3}, {%4,%5,%6,%7}, {%8,%9}, {%0,%1,%2,%3};"
        : "+f"(c[0]), "+f"(c[1]), "+f"(c[2]), "+f"(c[3])
        : "r"(a[0]), "r"(a[1]), "r"(a[2]), "r"(a[3]), "r"(b[0]), "r"(b[1]));
}

__global__ __launch_bounds__(256, 2) void gemm_mma_kernel(
        const float* __restrict__ x,
        const __half* __restrict__ wt,
        __half* __restrict__ hidden, int M) {
    extern __shared__ __half sm[];

    const int tid  = threadIdx.x;
    const int warp = tid >> 5;
    const int lane = tid & 31;
    const int gid  = lane >> 2;
    const int tig  = lane & 3;
    const int wm   = warp >> 1;
    const int wn   = warp & 1;
    const int blockM = blockIdx.y * 128;
    const int blockN = blockIdx.x * 64;

    // ---- load B tile (full K): 64 rows x 256 k ----
#pragma unroll
    for (int t = 0; t < 8; t++) {
        int idx = tid + t * 256;
        int n = idx >> 5;
        int j = idx & 31;
        *reinterpret_cast<uint4*>(&sm[B_OFF + n * SB + j * 8]) =
            *reinterpret_cast<const uint4*>(&wt[(size_t)(blockN + n) * DIM + j * 8]);
    }

    float c[2][4][4];
#pragma unroll
    for (int f = 0; f < 2; f++)
#pragma unroll
        for (int g = 0; g < 4; g++)
#pragma unroll
            for (int q = 0; q < 4; q++) c[f][g][q] = 0.f;

    for (int kc = 0; kc < 2; kc++) {          // two K=128 chunks
        __syncthreads();
        // ---- stage A chunk: x[blockM..+128, kc*128..+128] fp32 -> fp16 ----
#pragma unroll
        for (int t = 0; t < 16; t++) {
            int idx = tid + t * 256;          // 0..4095 float4 slots
            int row = idx >> 5;               // 0..127
            int c4  = idx & 31;               // float4 within 128-col chunk
            float4 v = make_float4(0.f, 0.f, 0.f, 0.f);
            if (blockM + row < M)
                v = *reinterpret_cast<const float4*>(
                        &x[(size_t)(blockM + row) * DIM + kc * 128 + c4 * 4]);
            __half2 p0 = __floats2half2_rn(v.x, v.y);
            __half2 p1 = __floats2half2_rn(v.z, v.w);
            *reinterpret_cast<uint2*>(&sm[A_OFF + row * SA + c4 * 4]) =
                make_uint2(*reinterpret_cast<uint32_t*>(&p0),
                           *reinterpret_cast<uint32_t*>(&p1));
        }
        __syncthreads();

#pragma unroll
        for (int ks = 0; ks < 8; ks++) {      // eight K=16 steps per chunk
            const int kb = ks * 16;
            uint32_t a[2][4], bb[4][2];
#pragma unroll
            for (int f = 0; f < 2; f++) {
                int r0 = wm * 32 + f * 16;
                a[f][0] = *reinterpret_cast<const uint32_t*>(&sm[A_OFF + (r0 + gid)     * SA + kb + 2 * tig]);
                a[f][1] = *reinterpret_cast<const uint32_t*>(&sm[A_OFF + (r0 + gid + 8) * SA + kb + 2 * tig]);
                a[f][2] = *reinterpret_cast<const uint32_t*>(&sm[A_OFF + (r0 + gid)     * SA + kb + 2 * tig + 8]);
                a[f][3] = *reinterpret_cast<const uint32_t*>(&sm[A_OFF + (r0 + gid + 8) * SA + kb + 2 * tig + 8]);
            }
#pragma unroll
            for (int g = 0; g < 4; g++) {
                int n0 = wn * 32 + g * 8;
                int kk = kc * 128 + kb + 2 * tig;
                bb[g][0] = *reinterpret_cast<const uint32_t*>(&sm[B_OFF + (n0 + gid) * SB + kk]);
                bb[g][1] = *reinterpret_cast<const uint32_t*>(&sm[B_OFF + (n0 + gid) * SB + kk + 8]);
            }
#pragma unroll
            for (int f = 0; f < 2; f++)
#pragma unroll
                for (int g = 0; g < 4; g++)
                    mma16816(c[f][g], a[f], bb[g]);
        }
    }

#pragma unroll
    for (int f = 0; f < 2; f++) {
#pragma unroll
        for (int g = 0; g < 4; g++) {
            int row = blockM + wm * 32 + f * 16 + gid;
            int col = blockN + wn * 32 + g * 8 + 2 * tig;
            if (row < M)
                *reinterpret_cast<__half2*>(&hidden[(size_t)row * DIM + col]) =
                    __floats2half2_rn(c[f][g][0], c[f][g][1]);
            if (row + 8 < M)
                *reinterpret_cast<__half2*>(&hidden[(size_t)(row + 8) * DIM + col]) =
                    __floats2half2_rn(c[f][g][2], c[f][g][3]);
        }
    }
}

// ===========================================================================
// ELL build: ONE scatter kernel.
// ===========================================================================
__global__ void ell_scatter_kernel(const int* __restrict__ rows,
                                   const int* __restrict__ cols,
                                   const float* __restrict__ vals,
                                   int*  __restrict__ counts,
                                   int2* __restrict__ ell,
                                   int*  __restrict__ ovf_cnt,
                                   int4* __restrict__ ovf,
                                   int E) {
    int i = blockIdx.x * blockDim.x + threadIdx.x;
    if (i < E) {
        int r   = rows[i];
        int pos = atomicAdd(&counts[r], 1);
        if (pos < ELLW) {
            ell[(size_t)r * ELLW + pos] = make_int2(cols[i], __float_as_int(vals[i]));
        } else {
            int o = atomicAdd(ovf_cnt, 1);
            if (o < OVF_CAP)
                ovf[o] = make_int4(r, cols[i], __float_as_int(vals[i]), 0);
        }
    }
}

// ===========================================================================
// SpMM (R11 scalar form — measured 40.7us): warp per dest row,
// lane owns 8 dims (one uint4 gather per edge), 8-edge unroll.
// ===========================================================================
__device__ __forceinline__ void fma8_half(float* acc, uint4 r, float v) {
    float2 f0 = __half22float2(*reinterpret_cast<__half2*>(&r.x));
    float2 f1 = __half22float2(*reinterpret_cast<__half2*>(&r.y));
    float2 f2 = __half22float2(*reinterpret_cast<__half2*>(&r.z));
    float2 f3 = __half22float2(*reinterpret_cast<__half2*>(&r.w));
    acc[0] = fmaf(v, f0.x, acc[0]); acc[1] = fmaf(v, f0.y, acc[1]);
    acc[2] = fmaf(v, f1.x, acc[2]); acc[3] = fmaf(v, f1.y, acc[3]);
    acc[4] = fmaf(v, f2.x, acc[4]); acc[5] = fmaf(v, f2.y, acc[5]);
    acc[6] = fmaf(v, f3.x, acc[6]); acc[7] = fmaf(v, f3.y, acc[7]);
}

__global__ __launch_bounds__(256) void spmm_ell_kernel(const int*  __restrict__ counts,
                                                       const int2* __restrict__ ell,
                                                       const __half* __restrict__ hidden,
                                                       const float* __restrict__ b,
                                                       float*       __restrict__ out,
                                                       int M) {
    const int w    = (blockIdx.x * blockDim.x + threadIdx.x) >> 5;
    const int lane = threadIdx.x & 31;
    if (w >= M) return;

    const int cnt = min(counts[w], ELLW);
    const int2* erow = ell + (size_t)w * ELLW;

    float acc[8];
#pragma unroll
    for (int q = 0; q < 8; q++) acc[q] = 0.f;
    const __half* hbase = hidden + lane * 8;

    int j = 0;
    for (; j + 7 < cnt; j += 8) {
        int2 p[8];
#pragma unroll
        for (int q = 0; q < 8; q++) p[q] = erow[j + q];
        uint4 r[8];
#pragma unroll
        for (int q = 0; q < 8; q++)
            r[q] = *reinterpret_cast<const uint4*>(hbase + (size_t)p[q].x * DIM);
#pragma unroll
        for (int q = 0; q < 8; q++)
            fma8_half(acc, r[q], __int_as_float(p[q].y));
    }
    for (; j + 3 < cnt; j += 4) {
        int2 p[4];
#pragma unroll
        for (int q = 0; q < 4; q++) p[q] = erow[j + q];
        uint4 r[4];
#pragma unroll
        for (int q = 0; q < 4; q++)
            r[q] = *reinterpret_cast<const uint4*>(hbase + (size_t)p[q].x * DIM);
#pragma unroll
        for (int q = 0; q < 4; q++)
            fma8_half(acc, r[q], __int_as_float(p[q].y));
    }
    for (; j < cnt; j++) {
        int2 p0 = erow[j];
        uint4 r0 = *reinterpret_cast<const uint4*>(hbase + (size_t)p0.x * DIM);
        fma8_half(acc, r0, __int_as_float(p0.y));
    }

    const float4* b4 = reinterpret_cast<const float4*>(b + lane * 8);
    float4 bb0 = b4[0], bb1 = b4[1];
    float4* o = reinterpret_cast<float4*>(out + (size_t)w * DIM + lane * 8);
    o[0] = make_float4(acc[0] + bb0.x, acc[1] + bb0.y, acc[2] + bb0.z, acc[3] + bb0.w);
    o[1] = make_float4(acc[4] + bb1.x, acc[5] + bb1.y, acc[6] + bb1.z, acc[7] + bb1.w);
}

// ===========================================================================
// Overflow fixup: normally n==0.
// ===========================================================================
__global__ void ovf_fixup_kernel(const int* __restrict__ ovf_cnt,
                                 const int4* __restrict__ ovf,
                                 const __half* __restrict__ hidden,
                                 float* __restrict__ out) {
    int n = min(*ovf_cnt, OVF_CAP);
    int t = threadIdx.x;
    for (int e = 0; e < n; e++) {
        int4 p = ovf[e];
        float v = __int_as_float(p.z);
        out[(size_t)p.x * DIM + t] =
            fmaf(v, __half2float(hidden[(size_t)p.y * DIM + t]),
                 out[(size_t)p.x * DIM + t]);
    }
}

// ===========================================================================
// Launch (unchanged structure):
//   s_csr  : memsets -> ell_scatter        (|| gemm)
//   default: wt -> gemm (grid 4x391) -> [wait ELL] spmm -> fixup
// ===========================================================================
extern "C" void kernel_launch(void* const* d_in, const int* in_sizes, int n_in,
                              void* d_out, int out_size) {
    const float* x        = (const float*)d_in[0];
    const int*   adj_rows = (const int*)  d_in[1];
    const int*   adj_cols = (const int*)  d_in[2];
    const float* adj_vals = (const float*)d_in[3];
    const float* W        = (const float*)d_in[4];
    const float* b        = (const float*)d_in[5];
    float*       out      = (float*)d_out;

    const int M = in_sizes[0] / DIM;   // 50000
    const int E = in_sizes[1];         // 800000

    __half *hidden, *wt;
    int *counts, *ovf_cnt;
    int2 *ell;
    int4 *ovf;
    cudaGetSymbolAddress((void**)&hidden,  g_hidden_h);
    cudaGetSymbolAddress((void**)&wt,      g_WT);
    cudaGetSymbolAddress((void**)&counts,  g_counts);
    cudaGetSymbolAddress((void**)&ell,     g_ell);
    cudaGetSymbolAddress((void**)&ovf_cnt, g_ovf_cnt);
    cudaGetSymbolAddress((void**)&ovf,     g_ovf);

    static cudaStream_t s_csr = nullptr;
    static cudaEvent_t  ev_fork = nullptr, ev_csr = nullptr;
    if (s_csr == nullptr) {
        cudaStreamCreateWithFlags(&s_csr, cudaStreamNonBlocking);
        cudaEventCreateWithFlags(&ev_fork, cudaEventDisableTiming);
        cudaEventCreateWithFlags(&ev_csr,  cudaEventDisableTiming);
        cudaFuncSetAttribute(gemm_mma_kernel,
                             cudaFuncAttributeMaxDynamicSharedMemorySize, GEMM_SMEM_BYTES);
    }

    // ---- fork: ELL build on s_csr ----
    cudaEventRecord(ev_fork, 0);
    cudaStreamWaitEvent(s_csr, ev_fork, 0);

    cudaMemsetAsync(counts, 0, (size_t)M * sizeof(int), s_csr);
    cudaMemsetAsync(ovf_cnt, 0, sizeof(int), s_csr);
    ell_scatter_kernel<<<(E + 255) / 256, 256, 0, s_csr>>>(adj_rows, adj_cols, adj_vals,
                                                           counts, ell, ovf_cnt, ovf, E);
    cudaEventRecord(ev_csr, s_csr);

    // ---- GEMM (single launch, 4 N-blocks co-resident, x shared via L2) ----
    wt_convert_kernel<<<DIM, DIM>>>(W, wt);
    dim3 gemmGrid(4, (M + 127) / 128);
    gemm_mma_kernel<<<gemmGrid, 256, GEMM_SMEM_BYTES>>>(x, wt, hidden, M);

    // ---- SpMM after GEMM + ELL ----
    cudaStreamWaitEvent(0, ev_csr, 0);
    spmm_ell_kernel<<<(M * 32 + 255) / 256, 256>>>(counts, ell, hidden, b, out, M);
    ovf_fixup_kernel<<<1, 256>>>(ovf_cnt, ovf, hidden, out);
}